// round 2
// baseline (speedup 1.0000x reference)
#include <cuda_runtime.h>
#include <cstddef>

#define R 64        // reduced channels
#define C 256       // channels
#define HH 96
#define WW 96
#define PIX (HH*WW)
#define NG 16       // groups
#define GC 16       // group channels
#define KT 7
#define KT2 49

// scratch for x = relu(BN(W1 @ guide)) : [8][64][96][96]
__device__ float g_x[8 * R * PIX];

// ---------------------------------------------------------------------------
// Kernel 1: x = relu(BN(W1 @ guide)) ; per-pixel GEMV, W1 in shared (transposed)
// grid (18, 8), block 512, dyn smem 64KB
// ---------------------------------------------------------------------------
__global__ __launch_bounds__(512) void k_convs1(
    const float* __restrict__ guide, const float* __restrict__ W1,
    const float* __restrict__ gamma, const float* __restrict__ beta,
    const float* __restrict__ mean,  const float* __restrict__ var)
{
    extern __shared__ float W1s[];     // [256][64] : W1s[c*64+o] = W1[o*256+c]
    __shared__ float sc[R], bi[R];

    int t = threadIdx.x;
    int b = blockIdx.y;
    int p = blockIdx.x * 512 + t;

    if (t < R) {
        float iv = gamma[t] * rsqrtf(var[t] + 1e-5f);
        sc[t] = iv;
        bi[t] = beta[t] - mean[t] * iv;
    }
    // transposed load: scattered global reads (L2-cached, 64KB matrix),
    // conflict-free shared stores, enables float4 broadcast reads in the loop
    for (int i = t; i < C * R; i += 512) {
        int o = i & 63, c = i >> 6;
        W1s[c * 64 + o] = W1[o * C + c];
    }
    __syncthreads();

    float acc[R];
#pragma unroll
    for (int o = 0; o < R; ++o) acc[o] = 0.f;

    const float* gp = guide + (size_t)b * C * PIX + p;
#pragma unroll 4
    for (int c = 0; c < C; ++c) {
        float gv = gp[(size_t)c * PIX];
        const float4* w4 = (const float4*)(W1s + c * 64);
#pragma unroll
        for (int q = 0; q < 16; ++q) {
            float4 w = w4[q];
            acc[4*q+0] += w.x * gv;
            acc[4*q+1] += w.y * gv;
            acc[4*q+2] += w.z * gv;
            acc[4*q+3] += w.w * gv;
        }
    }

    float* xp = g_x + (size_t)b * R * PIX + p;
#pragma unroll
    for (int o = 0; o < R; ++o) {
        xp[(size_t)o * PIX] = fmaxf(acc[o] * sc[o] + bi[o], 0.f);
    }
}

// ---------------------------------------------------------------------------
// Kernel 2: fused df-GEMM + involution + residual.
// Block = (batch b, row pair i0..i0+1), 512 threads = 2 teams x 256.
// Per group g: stage W2^g (transposed) + 16ch x 8row x 102col feature tile,
// GEMM df[49][96] into shared, then involution (2 channels/thread).
// grid (48, 8), block 512, dyn smem 150.75KB
// ---------------------------------------------------------------------------
__global__ __launch_bounds__(512) void k_invol(
    const float* __restrict__ feat, const float* __restrict__ W2,
    float* __restrict__ out)
{
    extern __shared__ float smem[];
    float* W2_s = smem;                    // [64][56]  (r-major, row kk inner)
    float* x_s  = W2_s + 64 * 56;          // [2][64][96]
    float* df_s = x_s  + 2 * R * WW;       // [2][49][96]
    float* ft   = df_s + 2 * KT2 * WW;     // [16][8][104] (rows i0-3..i0+4, cols -3..98)

    int t    = threadIdx.x;
    int b    = blockIdx.y;
    int i0   = blockIdx.x * 2;
    int team = t >> 8;                     // 0/1 -> row i0+team
    int tt   = t & 255;
    int i    = i0 + team;

    // stage x rows (once per block)
    for (int idx = t; idx < 2 * R * WW; idx += 512) {
        int tm  = idx / (R * WW);
        int rem = idx - tm * (R * WW);
        int r   = rem / WW;
        int j   = rem - r * WW;
        x_s[idx] = g_x[(((size_t)b * R + r) * HH + (i0 + tm)) * WW + j];
    }

    const int rI  = tt >> 5;               // GEMM: warp row-group 0..7
    const int cx  = tt & 31;               // GEMM: column lane
    const int u   = tt >> 5;               // invol: channel pair 0..7
    const int seg = tt & 31;               // invol: 3-col segment
    const int jb  = 3 * seg;

    for (int g = 0; g < NG; ++g) {
        __syncthreads();   // prior-iteration readers done; also x_s ready (iter 0)

        // stage W2^g transposed: W2_s[r*56+kk] = W2[(g*49+kk)*64+r]
        for (int idx = t; idx < KT2 * R; idx += 512) {
            int kk = idx >> 6, r = idx & 63;
            W2_s[r * 56 + kk] = W2[(size_t)(g * KT2) * R + idx];
        }
        // stage feature tile for this group's 16 channels (zero-padded halo)
        for (int idx = t; idx < GC * 8 * 102; idx += 512) {
            int ch  = idx / (8 * 102);
            int rem = idx - ch * (8 * 102);
            int rr  = rem / 102;
            int cc  = rem - rr * 102;
            int grow = i0 + rr - 3;
            int gcol = cc - 3;
            float v = 0.f;
            if (grow >= 0 && grow < HH && gcol >= 0 && gcol < WW)
                v = feat[(((size_t)b * C + g * GC + ch) * HH + grow) * WW + gcol];
            ft[(ch * 8 + rr) * 104 + cc] = v;
        }
        __syncthreads();

        // ---- GEMM: df[49][96] = W2^g[49][64] @ x_row[64][96] ----
        const float* xs  = x_s  + team * (R * WW);
        float*       dfs = df_s + team * (KT2 * WW);
        float a0[7], a1[7], a2[7];
#pragma unroll
        for (int jj = 0; jj < 7; ++jj) { a0[jj] = 0.f; a1[jj] = 0.f; a2[jj] = 0.f; }
#pragma unroll 4
        for (int r = 0; r < R; ++r) {
            float x0 = xs[r * 96 + cx];
            float x1 = xs[r * 96 + cx + 32];
            float x2 = xs[r * 96 + cx + 64];
            const float* wr = W2_s + r * 56 + rI;   // broadcast per warp
#pragma unroll
            for (int jj = 0; jj < 7; ++jj) {
                float wv = wr[8 * jj];
                a0[jj] += wv * x0;
                a1[jj] += wv * x1;
                a2[jj] += wv * x2;
            }
        }
#pragma unroll
        for (int jj = 0; jj < 7; ++jj) {
            int row = rI + 8 * jj;
            if (row < KT2) {
                dfs[row * 96 + cx]      = a0[jj];
                dfs[row * 96 + cx + 32] = a1[jj];
                dfs[row * 96 + cx + 64] = a2[jj];
            }
        }
        __syncthreads();

        // ---- involution: 2 channels x 3 cols per thread, residual fused ----
        int ch0 = 2 * u;
        const float* ft0 = ft + (ch0 * 8) * 104;
        const float* ft1 = ft + ((ch0 + 1) * 8) * 104;
        float o0[3], o1[3];
#pragma unroll
        for (int jj = 0; jj < 3; ++jj) {
            o0[jj] = ft0[(team + 3) * 104 + 3 + jb + jj];   // residual
            o1[jj] = ft1[(team + 3) * 104 + 3 + jb + jj];
        }
#pragma unroll
        for (int di = 0; di < KT; ++di) {
            float f0[9], f1[9];
            const float* r0p = ft0 + (team + di) * 104 + jb;
            const float* r1p = ft1 + (team + di) * 104 + jb;
#pragma unroll
            for (int q = 0; q < 9; ++q) { f0[q] = r0p[q]; f1[q] = r1p[q]; }
            const float* dp = dfs + (di * KT) * 96 + jb;
#pragma unroll
            for (int dj = 0; dj < KT; ++dj) {
                float d0 = dp[dj * 96 + 0];
                float d1 = dp[dj * 96 + 1];
                float d2 = dp[dj * 96 + 2];
                o0[0] += f0[dj]     * d0;
                o0[1] += f0[dj + 1] * d1;
                o0[2] += f0[dj + 2] * d2;
                o1[0] += f1[dj]     * d0;
                o1[1] += f1[dj + 1] * d1;
                o1[2] += f1[dj + 2] * d2;
            }
        }
        size_t ob = (((size_t)b * C + g * GC + ch0) * HH + i) * WW + jb;
#pragma unroll
        for (int jj = 0; jj < 3; ++jj) out[ob + jj]       = o0[jj];
#pragma unroll
        for (int jj = 0; jj < 3; ++jj) out[ob + PIX + jj] = o1[jj];
    }
}

// ---------------------------------------------------------------------------
extern "C" void kernel_launch(void* const* d_in, const int* in_sizes, int n_in,
                              void* d_out, int out_size)
{
    const float* feat  = (const float*)d_in[0];
    const float* guide = (const float*)d_in[1];
    const float* W1    = (const float*)d_in[2];
    const float* gamma = (const float*)d_in[3];
    const float* beta  = (const float*)d_in[4];
    const float* mean  = (const float*)d_in[5];
    const float* var   = (const float*)d_in[6];
    const float* W2    = (const float*)d_in[7];
    float* out = (float*)d_out;

    const int SMEM1 = C * R * (int)sizeof(float);                               // 65536
    const int SMEM2 = (64*56 + 2*R*WW + 2*KT2*WW + GC*8*104) * (int)sizeof(float); // 154368

    cudaFuncSetAttribute(k_convs1, cudaFuncAttributeMaxDynamicSharedMemorySize, SMEM1);
    cudaFuncSetAttribute(k_invol,  cudaFuncAttributeMaxDynamicSharedMemorySize, SMEM2);

    k_convs1<<<dim3(18, 8), 512, SMEM1>>>(guide, W1, gamma, beta, mean, var);
    k_invol<<<dim3(48, 8), 512, SMEM2>>>(feat, W2, out);
}

// round 3
// speedup vs baseline: 1.1190x; 1.1190x over previous
#include <cuda_runtime.h>
#include <cstddef>

#define R 64        // reduced channels
#define C 256       // channels
#define HH 96
#define WW 96
#define PIX (HH*WW)
#define NG 16       // groups
#define GC 16       // group channels
#define KT 7
#define KT2 49

// scratch for x = relu(BN(W1 @ guide)) : [8][64][96][96]
__device__ float g_x[8 * R * PIX];

// ---------------------------------------------------------------------------
// Kernel 1: x = relu(BN(W1 @ guide)) ; per-pixel GEMV, W1 in shared (transposed)
// grid (18, 8), block 512, dyn smem 64KB
// ---------------------------------------------------------------------------
__global__ __launch_bounds__(512) void k_convs1(
    const float* __restrict__ guide, const float* __restrict__ W1,
    const float* __restrict__ gamma, const float* __restrict__ beta,
    const float* __restrict__ mean,  const float* __restrict__ var)
{
    extern __shared__ float W1s[];     // [256][64] : W1s[c*64+o] = W1[o*256+c]
    __shared__ float sc[R], bi[R];

    int t = threadIdx.x;
    int b = blockIdx.y;
    int p = blockIdx.x * 512 + t;

    if (t < R) {
        float iv = gamma[t] * rsqrtf(var[t] + 1e-5f);
        sc[t] = iv;
        bi[t] = beta[t] - mean[t] * iv;
    }
    for (int i = t; i < C * R; i += 512) {
        int o = i & 63, c = i >> 6;
        W1s[c * 64 + o] = W1[o * C + c];
    }
    __syncthreads();

    float acc[R];
#pragma unroll
    for (int o = 0; o < R; ++o) acc[o] = 0.f;

    const float* gp = guide + (size_t)b * C * PIX + p;
#pragma unroll 4
    for (int c = 0; c < C; ++c) {
        float gv = gp[(size_t)c * PIX];
        const float4* w4 = (const float4*)(W1s + c * 64);
#pragma unroll
        for (int q = 0; q < 16; ++q) {
            float4 w = w4[q];
            acc[4*q+0] += w.x * gv;
            acc[4*q+1] += w.y * gv;
            acc[4*q+2] += w.z * gv;
            acc[4*q+3] += w.w * gv;
        }
    }

    float* xp = g_x + (size_t)b * R * PIX + p;
#pragma unroll
    for (int o = 0; o < R; ++o) {
        xp[(size_t)o * PIX] = fmaxf(acc[o] * sc[o] + bi[o], 0.f);
    }
}

// ---------------------------------------------------------------------------
// Kernel 2: fused df-GEMM + involution + residual.
// Block = (batch b, row pair i0..i0+1), 512 threads = 2 teams x 256.
// x is read straight from g_x via coalesced LDG (L2-resident, re-read 16x)
// instead of being staged in shared -> smem 105KB -> 2 CTAs/SM (occ 50%).
// grid (48, 8), block 512, dyn smem 102.75KB
// ---------------------------------------------------------------------------
__global__ __launch_bounds__(512, 2) void k_invol(
    const float* __restrict__ feat, const float* __restrict__ W2,
    float* __restrict__ out)
{
    extern __shared__ float smem[];
    float* W2_s = smem;                    // [64][56]  (r-major, row kk inner)
    float* df_s = W2_s + 64 * 56;          // [2][49][96]
    float* ft   = df_s + 2 * KT2 * WW;     // [16][8][104] (rows i0-3..i0+4, cols -3..98)

    int t    = threadIdx.x;
    int b    = blockIdx.y;
    int i0   = blockIdx.x * 2;
    int team = t >> 8;                     // 0/1 -> row i0+team
    int tt   = t & 255;
    int i    = i0 + team;

    const int rI  = tt >> 5;               // GEMM: warp row-group 0..7
    const int cx  = tt & 31;               // GEMM: column lane
    const int u   = tt >> 5;               // invol: channel pair 0..7
    const int seg = tt & 31;               // invol: 3-col segment
    const int jb  = 3 * seg;

    // per-team base of x row in global: g_x[b][r][i][:] with r-stride = PIX
    const float* xbase = g_x + (size_t)b * R * PIX + (size_t)i * WW;

    for (int g = 0; g < NG; ++g) {
        __syncthreads();   // prior-iteration readers of W2_s/ft/df_s done

        // stage W2^g transposed: W2_s[r*56+kk] = W2[(g*49+kk)*64+r]
        for (int idx = t; idx < KT2 * R; idx += 512) {
            int kk = idx >> 6, r = idx & 63;
            W2_s[r * 56 + kk] = W2[(size_t)(g * KT2) * R + idx];
        }
        // stage feature tile for this group's 16 channels (zero-padded halo)
        for (int idx = t; idx < GC * 8 * 102; idx += 512) {
            int ch  = idx / (8 * 102);
            int rem = idx - ch * (8 * 102);
            int rr  = rem / 102;
            int cc  = rem - rr * 102;
            int grow = i0 + rr - 3;
            int gcol = cc - 3;
            float v = 0.f;
            if (grow >= 0 && grow < HH && gcol >= 0 && gcol < WW)
                v = feat[(((size_t)b * C + g * GC + ch) * HH + grow) * WW + gcol];
            ft[(ch * 8 + rr) * 104 + cc] = v;
        }
        __syncthreads();

        // ---- GEMM: df[49][96] = W2^g[49][64] @ x_row[64][96] ----
        // x read directly from global (coalesced, L2-hot)
        float*       dfs = df_s + team * (KT2 * WW);
        float a0[7], a1[7], a2[7];
#pragma unroll
        for (int jj = 0; jj < 7; ++jj) { a0[jj] = 0.f; a1[jj] = 0.f; a2[jj] = 0.f; }
        const float* xp = xbase + cx;
#pragma unroll 4
        for (int r = 0; r < R; ++r) {
            float x0 = __ldg(xp);
            float x1 = __ldg(xp + 32);
            float x2 = __ldg(xp + 64);
            xp += PIX;
            const float* wr = W2_s + r * 56 + rI;   // broadcast per warp
#pragma unroll
            for (int jj = 0; jj < 7; ++jj) {
                float wv = wr[8 * jj];
                a0[jj] += wv * x0;
                a1[jj] += wv * x1;
                a2[jj] += wv * x2;
            }
        }
#pragma unroll
        for (int jj = 0; jj < 7; ++jj) {
            int row = rI + 8 * jj;
            if (row < KT2) {
                dfs[row * 96 + cx]      = a0[jj];
                dfs[row * 96 + cx + 32] = a1[jj];
                dfs[row * 96 + cx + 64] = a2[jj];
            }
        }
        __syncthreads();

        // ---- involution: 2 channels x 3 cols per thread, residual fused ----
        int ch0 = 2 * u;
        const float* ft0 = ft + (ch0 * 8) * 104;
        const float* ft1 = ft + ((ch0 + 1) * 8) * 104;
        float o0[3], o1[3];
#pragma unroll
        for (int jj = 0; jj < 3; ++jj) {
            o0[jj] = ft0[(team + 3) * 104 + 3 + jb + jj];   // residual
            o1[jj] = ft1[(team + 3) * 104 + 3 + jb + jj];
        }
#pragma unroll
        for (int di = 0; di < KT; ++di) {
            float f0[9], f1[9];
            const float* r0p = ft0 + (team + di) * 104 + jb;
            const float* r1p = ft1 + (team + di) * 104 + jb;
#pragma unroll
            for (int q = 0; q < 9; ++q) { f0[q] = r0p[q]; f1[q] = r1p[q]; }
            const float* dp = dfs + (di * KT) * 96 + jb;
#pragma unroll
            for (int dj = 0; dj < KT; ++dj) {
                float d0 = dp[dj * 96 + 0];
                float d1 = dp[dj * 96 + 1];
                float d2 = dp[dj * 96 + 2];
                o0[0] += f0[dj]     * d0;
                o0[1] += f0[dj + 1] * d1;
                o0[2] += f0[dj + 2] * d2;
                o1[0] += f1[dj]     * d0;
                o1[1] += f1[dj + 1] * d1;
                o1[2] += f1[dj + 2] * d2;
            }
        }
        size_t ob = (((size_t)b * C + g * GC + ch0) * HH + i) * WW + jb;
#pragma unroll
        for (int jj = 0; jj < 3; ++jj) out[ob + jj]       = o0[jj];
#pragma unroll
        for (int jj = 0; jj < 3; ++jj) out[ob + PIX + jj] = o1[jj];
    }
}

// ---------------------------------------------------------------------------
extern "C" void kernel_launch(void* const* d_in, const int* in_sizes, int n_in,
                              void* d_out, int out_size)
{
    const float* feat  = (const float*)d_in[0];
    const float* guide = (const float*)d_in[1];
    const float* W1    = (const float*)d_in[2];
    const float* gamma = (const float*)d_in[3];
    const float* beta  = (const float*)d_in[4];
    const float* mean  = (const float*)d_in[5];
    const float* var   = (const float*)d_in[6];
    const float* W2    = (const float*)d_in[7];
    float* out = (float*)d_out;

    const int SMEM1 = C * R * (int)sizeof(float);                            // 65536
    const int SMEM2 = (64*56 + 2*KT2*WW + GC*8*104) * (int)sizeof(float);    // 105216

    cudaFuncSetAttribute(k_convs1, cudaFuncAttributeMaxDynamicSharedMemorySize, SMEM1);
    cudaFuncSetAttribute(k_invol,  cudaFuncAttributeMaxDynamicSharedMemorySize, SMEM2);

    k_convs1<<<dim3(18, 8), 512, SMEM1>>>(guide, W1, gamma, beta, mean, var);
    k_invol<<<dim3(48, 8), 512, SMEM2>>>(feat, W2, out);
}

// round 5
// speedup vs baseline: 1.2749x; 1.1393x over previous
#include <cuda_runtime.h>
#include <cuda_bf16.h>
#include <cstdint>
#include <cstddef>

#define R 64        // reduced channels
#define C 256       // channels
#define HH 96
#define WW 96
#define PIX (HH*WW)
#define NG 16       // groups
#define GC 16       // group channels
#define KT 7
#define KT2 49
#define NPG 56      // padded filters per group (49 -> 56)

// scratch: x = relu(BN(W1 @ guide)) : [8][64][9216]
__device__ float g_x[8 * R * PIX];
// scratch: df = W2 @ x : [8][16][49][9216]  (231 MB)
__device__ float g_df[(size_t)8 * NG * KT2 * PIX];

// ---------------------------------------------------------------------------
// mma.sync m16n8k16 bf16 (row.col), fp32 accumulate — portable HMMA path
// ---------------------------------------------------------------------------
__device__ __forceinline__ void mma_bf16(
    float& c0, float& c1, float& c2, float& c3,
    uint32_t a0, uint32_t a1, uint32_t a2, uint32_t a3,
    uint32_t b0, uint32_t b1)
{
    asm volatile(
        "mma.sync.aligned.m16n8k16.row.col.f32.bf16.bf16.f32 "
        "{%0,%1,%2,%3}, {%4,%5,%6,%7}, {%8,%9}, {%0,%1,%2,%3};"
        : "+f"(c0), "+f"(c1), "+f"(c2), "+f"(c3)
        : "r"(a0), "r"(a1), "r"(a2), "r"(a3), "r"(b0), "r"(b1));
}

// ---------------------------------------------------------------------------
// Kernel 1: x = relu(BN(W1 @ guide))  (unchanged, passing since R2)
// ---------------------------------------------------------------------------
__global__ __launch_bounds__(512) void k_convs1(
    const float* __restrict__ guide, const float* __restrict__ W1,
    const float* __restrict__ gamma, const float* __restrict__ beta,
    const float* __restrict__ mean,  const float* __restrict__ var)
{
    extern __shared__ float W1s[];     // [256][64]
    __shared__ float sc[R], bi[R];

    int t = threadIdx.x;
    int b = blockIdx.y;
    int p = blockIdx.x * 512 + t;

    if (t < R) {
        float iv = gamma[t] * rsqrtf(var[t] + 1e-5f);
        sc[t] = iv;
        bi[t] = beta[t] - mean[t] * iv;
    }
    for (int i = t; i < C * R; i += 512) {
        int o = i & 63, c = i >> 6;
        W1s[c * 64 + o] = W1[o * C + c];
    }
    __syncthreads();

    float acc[R];
#pragma unroll
    for (int o = 0; o < R; ++o) acc[o] = 0.f;

    const float* gp = guide + (size_t)b * C * PIX + p;
#pragma unroll 4
    for (int c = 0; c < C; ++c) {
        float gv = gp[(size_t)c * PIX];
        const float4* w4 = (const float4*)(W1s + c * 64);
#pragma unroll
        for (int q = 0; q < 16; ++q) {
            float4 w = w4[q];
            acc[4*q+0] += w.x * gv;
            acc[4*q+1] += w.y * gv;
            acc[4*q+2] += w.z * gv;
            acc[4*q+3] += w.w * gv;
        }
    }
    float* xp = g_x + (size_t)b * R * PIX + p;
#pragma unroll
    for (int o = 0; o < R; ++o)
        xp[(size_t)o * PIX] = fmaxf(acc[o] * sc[o] + bi[o], 0.f);
}

// ---------------------------------------------------------------------------
// Kernel 2: df = W2 @ x via mma.sync bf16, 3-term split (hh + hl + lh).
// CTA: 256 thr = 8 warps (4 M x 2 N). Tile D[128 pix][112 cols = 2 groups].
// A = x^T [pix][k], B = W2 [col][k]; both bf16 hi/lo in smem, stride 72.
// grid (72, 8, 8), smem 69.1KB, 2 CTAs/SM.
// ---------------------------------------------------------------------------
#define LDA 72                 // padded k-stride (bf16 elems) for A and B
#define A_ELEMS (128 * LDA)    // 9216 bf16
#define B_ELEMS (112 * LDA)    // 8064 bf16
#define DS_LD 113              // epilogue stride (floats)

__global__ __launch_bounds__(256, 2) void k_dfgemm(const float* __restrict__ W2)
{
    extern __shared__ char smem[];
    __nv_bfloat16* Ah = (__nv_bfloat16*)smem;           // [128][72]
    __nv_bfloat16* Al = Ah + A_ELEMS;
    __nv_bfloat16* Bh = Al + A_ELEMS;                   // [112][72]
    __nv_bfloat16* Bl = Bh + B_ELEMS;
    float* Ds = (float*)smem;                           // [128][113] (reuse)

    const int t    = threadIdx.x;
    const int lane = t & 31;
    const int wid  = t >> 5;
    const int mw   = wid & 3;          // M-warp 0..3 -> pixels mw*32..+32
    const int nw   = wid >> 2;         // N-warp 0..1 -> cols  nw*56..+56
    const int b    = blockIdx.z;
    const int cb   = blockIdx.y * 112; // global col base (2 groups)
    const int p0   = blockIdx.x * 128;

    // ---- stage A: x[pix][k] hi/lo ----
    {
        const float* xb = g_x + (size_t)b * R * PIX + p0;
        int pix = t & 127;
        int rh  = t >> 7;   // 0/1
#pragma unroll
        for (int it = 0; it < 32; ++it) {
            int r = 2 * it + rh;
            float xv = xb[(size_t)r * PIX + pix];
            __nv_bfloat16 h = __float2bfloat16(xv);
            __nv_bfloat16 l = __float2bfloat16(xv - __bfloat162float(h));
            Ah[pix * LDA + r] = h;
            Al[pix * LDA + r] = l;
        }
    }
    // ---- stage B: W2[col][k] hi/lo (zero-pad kk>=49) ----
    {
#pragma unroll
        for (int it = 0; it < 28; ++it) {
            int idx = it * 256 + t;
            int col = idx >> 6, r = idx & 63;
            int g = col / NPG, kk = col - g * NPG;
            float wv = 0.f;
            if (kk < KT2) {
                int cg = (cb / NPG + g) * KT2 + kk;
                wv = W2[(size_t)cg * R + r];
            }
            __nv_bfloat16 h = __float2bfloat16(wv);
            __nv_bfloat16 l = __float2bfloat16(wv - __bfloat162float(h));
            Bh[col * LDA + r] = h;
            Bl[col * LDA + r] = l;
        }
    }
    __syncthreads();

    // ---- mma mainloop: K=64 in 4 steps of 16; 3-term split ----
    float acc[2][7][4];
#pragma unroll
    for (int mf = 0; mf < 2; ++mf)
#pragma unroll
        for (int nf = 0; nf < 7; ++nf)
#pragma unroll
            for (int q = 0; q < 4; ++q) acc[mf][nf][q] = 0.f;

    const int ar  = lane >> 2;         // fragment row
    const int ac  = (lane & 3) * 2;    // fragment col pair

#pragma unroll
    for (int ks = 0; ks < 4; ++ks) {
        const int kb = ks * 16;
        uint32_t ah[2][4], al[2][4];
#pragma unroll
        for (int mf = 0; mf < 2; ++mf) {
            int rb = mw * 32 + mf * 16;
            const __nv_bfloat16* pa = Ah + (rb + ar) * LDA + kb + ac;
            ah[mf][0] = *(const uint32_t*)pa;
            ah[mf][1] = *(const uint32_t*)(pa + 8 * LDA);
            ah[mf][2] = *(const uint32_t*)(pa + 8);
            ah[mf][3] = *(const uint32_t*)(pa + 8 * LDA + 8);
            const __nv_bfloat16* pl = Al + (rb + ar) * LDA + kb + ac;
            al[mf][0] = *(const uint32_t*)pl;
            al[mf][1] = *(const uint32_t*)(pl + 8 * LDA);
            al[mf][2] = *(const uint32_t*)(pl + 8);
            al[mf][3] = *(const uint32_t*)(pl + 8 * LDA + 8);
        }
#pragma unroll
        for (int nf = 0; nf < 7; ++nf) {
            int colb = nw * 56 + nf * 8 + ar;
            const __nv_bfloat16* pb = Bh + colb * LDA + kb + ac;
            uint32_t bh0 = *(const uint32_t*)pb;
            uint32_t bh1 = *(const uint32_t*)(pb + 8);
            const __nv_bfloat16* pbl = Bl + colb * LDA + kb + ac;
            uint32_t bl0 = *(const uint32_t*)pbl;
            uint32_t bl1 = *(const uint32_t*)(pbl + 8);
#pragma unroll
            for (int mf = 0; mf < 2; ++mf) {
                float* cc = acc[mf][nf];
                mma_bf16(cc[0], cc[1], cc[2], cc[3],
                         ah[mf][0], ah[mf][1], ah[mf][2], ah[mf][3], bh0, bh1);
                mma_bf16(cc[0], cc[1], cc[2], cc[3],
                         ah[mf][0], ah[mf][1], ah[mf][2], ah[mf][3], bl0, bl1);
                mma_bf16(cc[0], cc[1], cc[2], cc[3],
                         al[mf][0], al[mf][1], al[mf][2], al[mf][3], bh0, bh1);
            }
        }
    }
    __syncthreads();   // done reading A/B smem; reuse as Ds

    // ---- frags -> smem D[pix][col] ----
#pragma unroll
    for (int mf = 0; mf < 2; ++mf) {
        int row = mw * 32 + mf * 16 + ar;
#pragma unroll
        for (int nf = 0; nf < 7; ++nf) {
            int col = nw * 56 + nf * 8 + (lane & 3) * 2;
            Ds[row * DS_LD + col]           = acc[mf][nf][0];
            Ds[row * DS_LD + col + 1]       = acc[mf][nf][1];
            Ds[(row + 8) * DS_LD + col]     = acc[mf][nf][2];
            Ds[(row + 8) * DS_LD + col + 1] = acc[mf][nf][3];
        }
    }
    __syncthreads();

    // ---- coalesced store to g_df (skip padding cols kk>=49) ----
#pragma unroll
    for (int it = 0; it < 56; ++it) {
        int idx = it * 256 + t;
        int col = idx >> 7, pix = idx & 127;
        int g = col / NPG, kk = col - g * NPG;
        if (kk < KT2) {
            int gg = cb / NPG + g;
            g_df[(((size_t)(b * NG + gg)) * KT2 + kk) * PIX + p0 + pix] =
                Ds[pix * DS_LD + col];
        }
    }
}

// ---------------------------------------------------------------------------
// Kernel 3: involution + residual, df from global.
// Block = (batch b, row pair i0..i0+1), 512 threads = 2 teams x 256.
// grid (48, 8), smem 88.75KB, 2 CTAs/SM.
// ---------------------------------------------------------------------------
__global__ __launch_bounds__(512, 2) void k_invol(
    const float* __restrict__ feat, float* __restrict__ out)
{
    extern __shared__ float smemf[];
    float* df_s = smemf;                   // [49][192]  (2 rows x 96)
    float* ft   = df_s + KT2 * 192;        // [16][8][104]

    int t    = threadIdx.x;
    int b    = blockIdx.y;
    int i0   = blockIdx.x * 2;
    int team = t >> 8;
    int tt   = t & 255;
    int i    = i0 + team;

    const int u   = tt >> 5;               // channel pair 0..7
    const int seg = tt & 31;               // 3-col segment
    const int jb  = 3 * seg;

    for (int g = 0; g < NG; ++g) {
        __syncthreads();

        // stage df tile: rows i0, i0+1 for all 49 taps (contiguous pixels)
        const float* dfg = g_df + ((size_t)(b * NG + g) * KT2) * PIX + (size_t)i0 * WW;
        for (int idx = t; idx < KT2 * 192; idx += 512) {
            int kk = idx / 192, jj = idx - kk * 192;
            df_s[idx] = dfg[(size_t)kk * PIX + jj];
        }
        // stage feature tile (zero-padded halo)
        for (int idx = t; idx < GC * 8 * 102; idx += 512) {
            int ch  = idx / (8 * 102);
            int rem = idx - ch * (8 * 102);
            int rr  = rem / 102;
            int cc  = rem - rr * 102;
            int grow = i0 + rr - 3;
            int gcol = cc - 3;
            float v = 0.f;
            if (grow >= 0 && grow < HH && gcol >= 0 && gcol < WW)
                v = feat[(((size_t)b * C + g * GC + ch) * HH + grow) * WW + gcol];
            ft[(ch * 8 + rr) * 104 + cc] = v;
        }
        __syncthreads();

        // involution: 2 channels x 3 cols per thread, residual fused
        int ch0 = 2 * u;
        const float* ft0 = ft + (ch0 * 8) * 104;
        const float* ft1 = ft + ((ch0 + 1) * 8) * 104;
        const float* dbase = df_s + team * 96;
        float o0[3], o1[3];
#pragma unroll
        for (int jj = 0; jj < 3; ++jj) {
            o0[jj] = ft0[(team + 3) * 104 + 3 + jb + jj];   // residual
            o1[jj] = ft1[(team + 3) * 104 + 3 + jb + jj];
        }
#pragma unroll
        for (int di = 0; di < KT; ++di) {
            float f0[9], f1[9];
            const float* r0p = ft0 + (team + di) * 104 + jb;
            const float* r1p = ft1 + (team + di) * 104 + jb;
#pragma unroll
            for (int q = 0; q < 9; ++q) { f0[q] = r0p[q]; f1[q] = r1p[q]; }
            const float* dp = dbase + (di * KT) * 192 + jb;
#pragma unroll
            for (int dj = 0; dj < KT; ++dj) {
                float d0 = dp[dj * 192 + 0];
                float d1 = dp[dj * 192 + 1];
                float d2 = dp[dj * 192 + 2];
                o0[0] += f0[dj]     * d0;
                o0[1] += f0[dj + 1] * d1;
                o0[2] += f0[dj + 2] * d2;
                o1[0] += f1[dj]     * d0;
                o1[1] += f1[dj + 1] * d1;
                o1[2] += f1[dj + 2] * d2;
            }
        }
        size_t ob = (((size_t)b * C + g * GC + ch0) * HH + i) * WW + jb;
#pragma unroll
        for (int jj = 0; jj < 3; ++jj) out[ob + jj]       = o0[jj];
#pragma unroll
        for (int jj = 0; jj < 3; ++jj) out[ob + PIX + jj] = o1[jj];
    }
}

// ---------------------------------------------------------------------------
extern "C" void kernel_launch(void* const* d_in, const int* in_sizes, int n_in,
                              void* d_out, int out_size)
{
    const float* feat  = (const float*)d_in[0];
    const float* guide = (const float*)d_in[1];
    const float* W1    = (const float*)d_in[2];
    const float* gamma = (const float*)d_in[3];
    const float* beta  = (const float*)d_in[4];
    const float* mean  = (const float*)d_in[5];
    const float* var   = (const float*)d_in[6];
    const float* W2    = (const float*)d_in[7];
    float* out = (float*)d_out;

    const int SMEM1 = C * R * (int)sizeof(float);                       // 65536
    const int SMEM2 = 2 * (A_ELEMS + B_ELEMS) * (int)sizeof(__nv_bfloat16); // 69120
    const int SMEM3 = (KT2 * 192 + GC * 8 * 104) * (int)sizeof(float);  // 90880

    cudaFuncSetAttribute(k_convs1, cudaFuncAttributeMaxDynamicSharedMemorySize, SMEM1);
    cudaFuncSetAttribute(k_dfgemm, cudaFuncAttributeMaxDynamicSharedMemorySize, SMEM2);
    cudaFuncSetAttribute(k_invol,  cudaFuncAttributeMaxDynamicSharedMemorySize, SMEM3);

    k_convs1<<<dim3(18, 8), 512, SMEM1>>>(guide, W1, gamma, beta, mean, var);
    k_dfgemm<<<dim3(72, 8, 8), 256, SMEM2>>>(W2);
    k_invol<<<dim3(48, 8), 512, SMEM3>>>(feat, out);
}

// round 6
// speedup vs baseline: 1.2764x; 1.0011x over previous
#include <cuda_runtime.h>
#include <cuda_bf16.h>
#include <cstdint>
#include <cstddef>

#define R 64        // reduced channels
#define C 256       // channels
#define HH 96
#define WW 96
#define PIX (HH*WW)
#define NG 16       // groups
#define GC 16       // group channels
#define KT 7
#define KT2 49
#define NPG 56      // padded filters per group (49 -> 56)

// scratch: x = relu(BN(W1 @ guide)) : [8][64][9216]
__device__ float g_x[8 * R * PIX];
// scratch: df = W2 @ x : [8][16][49][9216]  (231 MB)
__device__ float g_df[(size_t)8 * NG * KT2 * PIX];

// ---------------------------------------------------------------------------
// mma.sync m16n8k16 bf16 (row.col), fp32 accumulate — portable HMMA path
// ---------------------------------------------------------------------------
__device__ __forceinline__ void mma_bf16(
    float& c0, float& c1, float& c2, float& c3,
    uint32_t a0, uint32_t a1, uint32_t a2, uint32_t a3,
    uint32_t b0, uint32_t b1)
{
    asm volatile(
        "mma.sync.aligned.m16n8k16.row.col.f32.bf16.bf16.f32 "
        "{%0,%1,%2,%3}, {%4,%5,%6,%7}, {%8,%9}, {%0,%1,%2,%3};"
        : "+f"(c0), "+f"(c1), "+f"(c2), "+f"(c3)
        : "r"(a0), "r"(a1), "r"(a2), "r"(a3), "r"(b0), "r"(b1));
}

// ---------------------------------------------------------------------------
// Kernel 1: x = relu(BN(W1 @ guide))  (unchanged, passing since R2)
// ---------------------------------------------------------------------------
__global__ __launch_bounds__(512) void k_convs1(
    const float* __restrict__ guide, const float* __restrict__ W1,
    const float* __restrict__ gamma, const float* __restrict__ beta,
    const float* __restrict__ mean,  const float* __restrict__ var)
{
    extern __shared__ float W1s[];     // [256][64]
    __shared__ float sc[R], bi[R];

    int t = threadIdx.x;
    int b = blockIdx.y;
    int p = blockIdx.x * 512 + t;

    if (t < R) {
        float iv = gamma[t] * rsqrtf(var[t] + 1e-5f);
        sc[t] = iv;
        bi[t] = beta[t] - mean[t] * iv;
    }
    for (int i = t; i < C * R; i += 512) {
        int o = i & 63, c = i >> 6;
        W1s[c * 64 + o] = W1[o * C + c];
    }
    __syncthreads();

    float acc[R];
#pragma unroll
    for (int o = 0; o < R; ++o) acc[o] = 0.f;

    const float* gp = guide + (size_t)b * C * PIX + p;
#pragma unroll 4
    for (int c = 0; c < C; ++c) {
        float gv = gp[(size_t)c * PIX];
        const float4* w4 = (const float4*)(W1s + c * 64);
#pragma unroll
        for (int q = 0; q < 16; ++q) {
            float4 w = w4[q];
            acc[4*q+0] += w.x * gv;
            acc[4*q+1] += w.y * gv;
            acc[4*q+2] += w.z * gv;
            acc[4*q+3] += w.w * gv;
        }
    }
    float* xp = g_x + (size_t)b * R * PIX + p;
#pragma unroll
    for (int o = 0; o < R; ++o)
        xp[(size_t)o * PIX] = fmaxf(acc[o] * sc[o] + bi[o], 0.f);
}

// ---------------------------------------------------------------------------
// Kernel 2: df = W2 @ x via mma.sync bf16, 3-term split (hh + hl + lh).
// CTA: 256 thr = 8 warps (4 M x 2 N). Tile D[128 pix][112 cols = 2 groups].
// A = x^T [pix][k], B = W2 [col][k]; both bf16 hi/lo in smem, stride 72.
// grid (72, 8, 8), smem 69.1KB, 2 CTAs/SM.
// ---------------------------------------------------------------------------
#define LDA 72                 // padded k-stride (bf16 elems) for A and B
#define A_ELEMS (128 * LDA)    // 9216 bf16
#define B_ELEMS (112 * LDA)    // 8064 bf16
#define DS_LD 113              // epilogue stride (floats)

__global__ __launch_bounds__(256, 2) void k_dfgemm(const float* __restrict__ W2)
{
    extern __shared__ char smem[];
    __nv_bfloat16* Ah = (__nv_bfloat16*)smem;           // [128][72]
    __nv_bfloat16* Al = Ah + A_ELEMS;
    __nv_bfloat16* Bh = Al + A_ELEMS;                   // [112][72]
    __nv_bfloat16* Bl = Bh + B_ELEMS;
    float* Ds = (float*)smem;                           // [128][113] (reuse)

    const int t    = threadIdx.x;
    const int lane = t & 31;
    const int wid  = t >> 5;
    const int mw   = wid & 3;          // M-warp 0..3 -> pixels mw*32..+32
    const int nw   = wid >> 2;         // N-warp 0..1 -> cols  nw*56..+56
    const int b    = blockIdx.z;
    const int cb   = blockIdx.y * 112; // global col base (2 groups)
    const int p0   = blockIdx.x * 128;

    // ---- stage A: x[pix][k] hi/lo ----
    {
        const float* xb = g_x + (size_t)b * R * PIX + p0;
        int pix = t & 127;
        int rh  = t >> 7;   // 0/1
#pragma unroll
        for (int it = 0; it < 32; ++it) {
            int r = 2 * it + rh;
            float xv = xb[(size_t)r * PIX + pix];
            __nv_bfloat16 h = __float2bfloat16(xv);
            __nv_bfloat16 l = __float2bfloat16(xv - __bfloat162float(h));
            Ah[pix * LDA + r] = h;
            Al[pix * LDA + r] = l;
        }
    }
    // ---- stage B: W2[col][k] hi/lo (zero-pad kk>=49) ----
    {
#pragma unroll
        for (int it = 0; it < 28; ++it) {
            int idx = it * 256 + t;
            int col = idx >> 6, r = idx & 63;
            int g = col / NPG, kk = col - g * NPG;
            float wv = 0.f;
            if (kk < KT2) {
                int cg = (cb / NPG + g) * KT2 + kk;
                wv = W2[(size_t)cg * R + r];
            }
            __nv_bfloat16 h = __float2bfloat16(wv);
            __nv_bfloat16 l = __float2bfloat16(wv - __bfloat162float(h));
            Bh[col * LDA + r] = h;
            Bl[col * LDA + r] = l;
        }
    }
    __syncthreads();

    // ---- mma mainloop: K=64 in 4 steps of 16; 3-term split ----
    float acc[2][7][4];
#pragma unroll
    for (int mf = 0; mf < 2; ++mf)
#pragma unroll
        for (int nf = 0; nf < 7; ++nf)
#pragma unroll
            for (int q = 0; q < 4; ++q) acc[mf][nf][q] = 0.f;

    const int ar  = lane >> 2;         // fragment row
    const int ac  = (lane & 3) * 2;    // fragment col pair

#pragma unroll
    for (int ks = 0; ks < 4; ++ks) {
        const int kb = ks * 16;
        uint32_t ah[2][4], al[2][4];
#pragma unroll
        for (int mf = 0; mf < 2; ++mf) {
            int rb = mw * 32 + mf * 16;
            const __nv_bfloat16* pa = Ah + (rb + ar) * LDA + kb + ac;
            ah[mf][0] = *(const uint32_t*)pa;
            ah[mf][1] = *(const uint32_t*)(pa + 8 * LDA);
            ah[mf][2] = *(const uint32_t*)(pa + 8);
            ah[mf][3] = *(const uint32_t*)(pa + 8 * LDA + 8);
            const __nv_bfloat16* pl = Al + (rb + ar) * LDA + kb + ac;
            al[mf][0] = *(const uint32_t*)pl;
            al[mf][1] = *(const uint32_t*)(pl + 8 * LDA);
            al[mf][2] = *(const uint32_t*)(pl + 8);
            al[mf][3] = *(const uint32_t*)(pl + 8 * LDA + 8);
        }
#pragma unroll
        for (int nf = 0; nf < 7; ++nf) {
            int colb = nw * 56 + nf * 8 + ar;
            const __nv_bfloat16* pb = Bh + colb * LDA + kb + ac;
            uint32_t bh0 = *(const uint32_t*)pb;
            uint32_t bh1 = *(const uint32_t*)(pb + 8);
            const __nv_bfloat16* pbl = Bl + colb * LDA + kb + ac;
            uint32_t bl0 = *(const uint32_t*)pbl;
            uint32_t bl1 = *(const uint32_t*)(pbl + 8);
#pragma unroll
            for (int mf = 0; mf < 2; ++mf) {
                float* cc = acc[mf][nf];
                mma_bf16(cc[0], cc[1], cc[2], cc[3],
                         ah[mf][0], ah[mf][1], ah[mf][2], ah[mf][3], bh0, bh1);
                mma_bf16(cc[0], cc[1], cc[2], cc[3],
                         ah[mf][0], ah[mf][1], ah[mf][2], ah[mf][3], bl0, bl1);
                mma_bf16(cc[0], cc[1], cc[2], cc[3],
                         al[mf][0], al[mf][1], al[mf][2], al[mf][3], bh0, bh1);
            }
        }
    }
    __syncthreads();   // done reading A/B smem; reuse as Ds

    // ---- frags -> smem D[pix][col] ----
#pragma unroll
    for (int mf = 0; mf < 2; ++mf) {
        int row = mw * 32 + mf * 16 + ar;
#pragma unroll
        for (int nf = 0; nf < 7; ++nf) {
            int col = nw * 56 + nf * 8 + (lane & 3) * 2;
            Ds[row * DS_LD + col]           = acc[mf][nf][0];
            Ds[row * DS_LD + col + 1]       = acc[mf][nf][1];
            Ds[(row + 8) * DS_LD + col]     = acc[mf][nf][2];
            Ds[(row + 8) * DS_LD + col + 1] = acc[mf][nf][3];
        }
    }
    __syncthreads();

    // ---- coalesced store to g_df (skip padding cols kk>=49) ----
#pragma unroll
    for (int it = 0; it < 56; ++it) {
        int idx = it * 256 + t;
        int col = idx >> 7, pix = idx & 127;
        int g = col / NPG, kk = col - g * NPG;
        if (kk < KT2) {
            int gg = cb / NPG + g;
            g_df[(((size_t)(b * NG + gg)) * KT2 + kk) * PIX + p0 + pix] =
                Ds[pix * DS_LD + col];
        }
    }
}

// ---------------------------------------------------------------------------
// Kernel 3: involution + residual, df from global.
// Block = (batch b, row pair i0..i0+1), 512 threads = 2 teams x 256.
// grid (48, 8), smem 88.75KB, 2 CTAs/SM.
// ---------------------------------------------------------------------------
__global__ __launch_bounds__(512, 2) void k_invol(
    const float* __restrict__ feat, float* __restrict__ out)
{
    extern __shared__ float smemf[];
    float* df_s = smemf;                   // [49][192]  (2 rows x 96)
    float* ft   = df_s + KT2 * 192;        // [16][8][104]

    int t    = threadIdx.x;
    int b    = blockIdx.y;
    int i0   = blockIdx.x * 2;
    int team = t >> 8;
    int tt   = t & 255;
    int i    = i0 + team;

    const int u   = tt >> 5;               // channel pair 0..7
    const int seg = tt & 31;               // 3-col segment
    const int jb  = 3 * seg;

    for (int g = 0; g < NG; ++g) {
        __syncthreads();

        // stage df tile: rows i0, i0+1 for all 49 taps (contiguous pixels)
        const float* dfg = g_df + ((size_t)(b * NG + g) * KT2) * PIX + (size_t)i0 * WW;
        for (int idx = t; idx < KT2 * 192; idx += 512) {
            int kk = idx / 192, jj = idx - kk * 192;
            df_s[idx] = dfg[(size_t)kk * PIX + jj];
        }
        // stage feature tile (zero-padded halo)
        for (int idx = t; idx < GC * 8 * 102; idx += 512) {
            int ch  = idx / (8 * 102);
            int rem = idx - ch * (8 * 102);
            int rr  = rem / 102;
            int cc  = rem - rr * 102;
            int grow = i0 + rr - 3;
            int gcol = cc - 3;
            float v = 0.f;
            if (grow >= 0 && grow < HH && gcol >= 0 && gcol < WW)
                v = feat[(((size_t)b * C + g * GC + ch) * HH + grow) * WW + gcol];
            ft[(ch * 8 + rr) * 104 + cc] = v;
        }
        __syncthreads();

        // involution: 2 channels x 3 cols per thread, residual fused
        int ch0 = 2 * u;
        const float* ft0 = ft + (ch0 * 8) * 104;
        const float* ft1 = ft + ((ch0 + 1) * 8) * 104;
        const float* dbase = df_s + team * 96;
        float o0[3], o1[3];
#pragma unroll
        for (int jj = 0; jj < 3; ++jj) {
            o0[jj] = ft0[(team + 3) * 104 + 3 + jb + jj];   // residual
            o1[jj] = ft1[(team + 3) * 104 + 3 + jb + jj];
        }
#pragma unroll
        for (int di = 0; di < KT; ++di) {
            float f0[9], f1[9];
            const float* r0p = ft0 + (team + di) * 104 + jb;
            const float* r1p = ft1 + (team + di) * 104 + jb;
#pragma unroll
            for (int q = 0; q < 9; ++q) { f0[q] = r0p[q]; f1[q] = r1p[q]; }
            const float* dp = dbase + (di * KT) * 192 + jb;
#pragma unroll
            for (int dj = 0; dj < KT; ++dj) {
                float d0 = dp[dj * 192 + 0];
                float d1 = dp[dj * 192 + 1];
                float d2 = dp[dj * 192 + 2];
                o0[0] += f0[dj]     * d0;
                o0[1] += f0[dj + 1] * d1;
                o0[2] += f0[dj + 2] * d2;
                o1[0] += f1[dj]     * d0;
                o1[1] += f1[dj + 1] * d1;
                o1[2] += f1[dj + 2] * d2;
            }
        }
        size_t ob = (((size_t)b * C + g * GC + ch0) * HH + i) * WW + jb;
#pragma unroll
        for (int jj = 0; jj < 3; ++jj) out[ob + jj]       = o0[jj];
#pragma unroll
        for (int jj = 0; jj < 3; ++jj) out[ob + PIX + jj] = o1[jj];
    }
}

// ---------------------------------------------------------------------------
extern "C" void kernel_launch(void* const* d_in, const int* in_sizes, int n_in,
                              void* d_out, int out_size)
{
    const float* feat  = (const float*)d_in[0];
    const float* guide = (const float*)d_in[1];
    const float* W1    = (const float*)d_in[2];
    const float* gamma = (const float*)d_in[3];
    const float* beta  = (const float*)d_in[4];
    const float* mean  = (const float*)d_in[5];
    const float* var   = (const float*)d_in[6];
    const float* W2    = (const float*)d_in[7];
    float* out = (float*)d_out;

    const int SMEM1 = C * R * (int)sizeof(float);                       // 65536
    const int SMEM2 = 2 * (A_ELEMS + B_ELEMS) * (int)sizeof(__nv_bfloat16); // 69120
    const int SMEM3 = (KT2 * 192 + GC * 8 * 104) * (int)sizeof(float);  // 90880

    cudaFuncSetAttribute(k_convs1, cudaFuncAttributeMaxDynamicSharedMemorySize, SMEM1);
    cudaFuncSetAttribute(k_dfgemm, cudaFuncAttributeMaxDynamicSharedMemorySize, SMEM2);
    cudaFuncSetAttribute(k_invol,  cudaFuncAttributeMaxDynamicSharedMemorySize, SMEM3);

    k_convs1<<<dim3(18, 8), 512, SMEM1>>>(guide, W1, gamma, beta, mean, var);
    k_dfgemm<<<dim3(72, 8, 8), 256, SMEM2>>>(W2);
    k_invol<<<dim3(48, 8), 512, SMEM3>>>(feat, out);
}

// round 7
// speedup vs baseline: 1.8963x; 1.4857x over previous
#include <cuda_runtime.h>
#include <cuda_bf16.h>
#include <cstdint>
#include <cstddef>

#define R 64        // reduced channels
#define C 256       // channels
#define HH 96
#define WW 96
#define PIX (HH*WW)
#define NG 16       // groups
#define GC 16       // group channels
#define KT 7
#define KT2 49

// x = relu(BN(W1 @ guide)), stored pre-split as bf16 hi/lo: [b][pix][r]
__device__ __nv_bfloat16 g_xh[(size_t)8 * PIX * R];
__device__ __nv_bfloat16 g_xl[(size_t)8 * PIX * R];

#define LDK 72                 // padded k-stride (bf16 elems) in smem tiles

// ---------------------------------------------------------------------------
// mma.sync m16n8k16 bf16 (row.col), fp32 accumulate (verified mapping, R5)
// ---------------------------------------------------------------------------
__device__ __forceinline__ void mma_bf16(
    float& c0, float& c1, float& c2, float& c3,
    uint32_t a0, uint32_t a1, uint32_t a2, uint32_t a3,
    uint32_t b0, uint32_t b1)
{
    asm volatile(
        "mma.sync.aligned.m16n8k16.row.col.f32.bf16.bf16.f32 "
        "{%0,%1,%2,%3}, {%4,%5,%6,%7}, {%8,%9}, {%0,%1,%2,%3};"
        : "+f"(c0), "+f"(c1), "+f"(c2), "+f"(c3)
        : "r"(a0), "r"(a1), "r"(a2), "r"(a3), "r"(b0), "r"(b1));
}

// ---------------------------------------------------------------------------
// Kernel 1: x = relu(BN(W1 @ guide)) via mma.sync, 3-term bf16 split.
// CTA: 256 thr = 8 warps (4M x 2N). D[192 pix][64 out], K=256 in 4 chunks.
// Epilogue: BN+ReLU, split to bf16 hi/lo, store [pix][r] layout.
// grid (48, 8), smem 72KB, 2 CTAs/SM.
// ---------------------------------------------------------------------------
#define C1_AH 0
#define C1_AL (192 * LDK)             // bf16 elems
#define C1_BH (2 * 192 * LDK)
#define C1_BL (2 * 192 * LDK + 64 * LDK)
#define C1_SMEM ((2 * 192 * LDK + 2 * 64 * LDK) * 2)   // 73728 bytes

__global__ __launch_bounds__(256, 2) void k_convs1(
    const float* __restrict__ guide, const float* __restrict__ W1,
    const float* __restrict__ gamma, const float* __restrict__ beta,
    const float* __restrict__ mean,  const float* __restrict__ var)
{
    extern __shared__ __nv_bfloat16 sm[];
    __nv_bfloat16* Ah = sm + C1_AH;
    __nv_bfloat16* Al = sm + C1_AL;
    __nv_bfloat16* Bh = sm + C1_BH;
    __nv_bfloat16* Bl = sm + C1_BL;
    __shared__ float sc[R], bi[R];

    const int t    = threadIdx.x;
    const int lane = t & 31;
    const int wid  = t >> 5;
    const int mw   = wid & 3;
    const int nw   = wid >> 2;
    const int b    = blockIdx.y;
    const int p0   = blockIdx.x * 192;

    if (t < R) {
        float iv = gamma[t] * rsqrtf(var[t] + 1e-5f);
        sc[t] = iv;
        bi[t] = beta[t] - mean[t] * iv;
    }

    float acc[3][4][4];
#pragma unroll
    for (int mf = 0; mf < 3; ++mf)
#pragma unroll
        for (int nf = 0; nf < 4; ++nf)
#pragma unroll
            for (int q = 0; q < 4; ++q) acc[mf][nf][q] = 0.f;

    const int ar = lane >> 2;
    const int ac = (lane & 3) * 2;

    for (int kc = 0; kc < 4; ++kc) {
        __syncthreads();   // prior mma readers done (also orders sc/bi, iter 0)
        // stage A: guide^T[192 pix][64 k] hi/lo
#pragma unroll
        for (int it = 0; it < 48; ++it) {
            int idx = it * 256 + t;
            int k   = idx / 192;
            int pix = idx - k * 192;
            float v = guide[(size_t)b * C * PIX + (size_t)(kc * 64 + k) * PIX + p0 + pix];
            __nv_bfloat16 h = __float2bfloat16(v);
            __nv_bfloat16 l = __float2bfloat16(v - __bfloat162float(h));
            Ah[pix * LDK + k] = h;
            Al[pix * LDK + k] = l;
        }
        // stage B: W1[64 out][64 k] hi/lo
#pragma unroll
        for (int it = 0; it < 16; ++it) {
            int idx = it * 256 + t;
            int col = idx >> 6, r = idx & 63;
            float wv = W1[(size_t)col * C + kc * 64 + r];
            __nv_bfloat16 h = __float2bfloat16(wv);
            __nv_bfloat16 l = __float2bfloat16(wv - __bfloat162float(h));
            Bh[col * LDK + r] = h;
            Bl[col * LDK + r] = l;
        }
        __syncthreads();

#pragma unroll
        for (int ks = 0; ks < 4; ++ks) {
            const int kb = ks * 16;
            uint32_t ah[3][4], al[3][4];
#pragma unroll
            for (int mf = 0; mf < 3; ++mf) {
                int rb = mw * 48 + mf * 16;
                const __nv_bfloat16* pa = Ah + (rb + ar) * LDK + kb + ac;
                ah[mf][0] = *(const uint32_t*)pa;
                ah[mf][1] = *(const uint32_t*)(pa + 8 * LDK);
                ah[mf][2] = *(const uint32_t*)(pa + 8);
                ah[mf][3] = *(const uint32_t*)(pa + 8 * LDK + 8);
                const __nv_bfloat16* pl = Al + (rb + ar) * LDK + kb + ac;
                al[mf][0] = *(const uint32_t*)pl;
                al[mf][1] = *(const uint32_t*)(pl + 8 * LDK);
                al[mf][2] = *(const uint32_t*)(pl + 8);
                al[mf][3] = *(const uint32_t*)(pl + 8 * LDK + 8);
            }
#pragma unroll
            for (int nf = 0; nf < 4; ++nf) {
                int colb = nw * 32 + nf * 8 + ar;
                const __nv_bfloat16* pb = Bh + colb * LDK + kb + ac;
                uint32_t bh0 = *(const uint32_t*)pb;
                uint32_t bh1 = *(const uint32_t*)(pb + 8);
                const __nv_bfloat16* pbl = Bl + colb * LDK + kb + ac;
                uint32_t bl0 = *(const uint32_t*)pbl;
                uint32_t bl1 = *(const uint32_t*)(pbl + 8);
#pragma unroll
                for (int mf = 0; mf < 3; ++mf) {
                    float* cc = acc[mf][nf];
                    mma_bf16(cc[0], cc[1], cc[2], cc[3],
                             ah[mf][0], ah[mf][1], ah[mf][2], ah[mf][3], bh0, bh1);
                    mma_bf16(cc[0], cc[1], cc[2], cc[3],
                             ah[mf][0], ah[mf][1], ah[mf][2], ah[mf][3], bl0, bl1);
                    mma_bf16(cc[0], cc[1], cc[2], cc[3],
                             al[mf][0], al[mf][1], al[mf][2], al[mf][3], bh0, bh1);
                }
            }
        }
    }

    // epilogue: BN + ReLU + hi/lo split, store [b][pix][r] packed u32 (2 bf16)
#pragma unroll
    for (int mf = 0; mf < 3; ++mf) {
        int row = mw * 48 + mf * 16 + ar;
#pragma unroll
        for (int nf = 0; nf < 4; ++nf) {
            int col = nw * 32 + nf * 8 + (lane & 3) * 2;
            float s0 = sc[col], s1 = sc[col + 1];
            float b0 = bi[col], b1 = bi[col + 1];
#pragma unroll
            for (int half = 0; half < 2; ++half) {
                int r2 = row + half * 8;
                float v0 = fmaxf(acc[mf][nf][2 * half + 0] * s0 + b0, 0.f);
                float v1 = fmaxf(acc[mf][nf][2 * half + 1] * s1 + b1, 0.f);
                __nv_bfloat162 h2 = __floats2bfloat162_rn(v0, v1);
                __nv_bfloat162 l2 = __floats2bfloat162_rn(
                    v0 - __bfloat162float(h2.x), v1 - __bfloat162float(h2.y));
                size_t base = ((size_t)b * PIX + p0 + r2) * R + col;
                *(uint32_t*)(g_xh + base) = *(uint32_t*)&h2;
                *(uint32_t*)(g_xl + base) = *(uint32_t*)&l2;
            }
        }
    }
}

// ---------------------------------------------------------------------------
// Kernel 2 (fused): per CTA = (row pair i0, group g, batch b).
//   Phase 1: df[192 pix][49(pad64)] = x^T @ W2^g^T via mma (3-term split)
//   Phase 2: acc -> smem Ds[192][53] fp32 ; stage feature tile [16][8][105]
//   Phase 3: involution + residual, all operands in smem. df never hits DRAM.
// grid (48, 16, 8), 256 thr, smem 94464B, 2 CTAs/SM.
// ---------------------------------------------------------------------------
#define F_AH 0
#define F_AL (192 * LDK)
#define F_BH (2 * 192 * LDK)
#define F_BL (2 * 192 * LDK + 64 * LDK)
#define F_FT_STRIDE 105
#define F_FT_FLOATS (GC * 8 * F_FT_STRIDE)         // 13440
#define F_DS_OFF    F_FT_FLOATS                    // floats
#define F_DS_LD     53
#define F_SMEM ((F_FT_FLOATS + 192 * F_DS_LD) * 4) // 94464 bytes

__global__ __launch_bounds__(256, 2) void k_fused(
    const float* __restrict__ feat, const float* __restrict__ W2,
    float* __restrict__ out)
{
    extern __shared__ __nv_bfloat16 sm[];
    __nv_bfloat16* Ah = sm + F_AH;
    __nv_bfloat16* Al = sm + F_AL;
    __nv_bfloat16* Bh = sm + F_BH;
    __nv_bfloat16* Bl = sm + F_BL;
    float* ft = (float*)sm;                 // phase-2/3 overlay
    float* Ds = (float*)sm + F_DS_OFF;

    const int t    = threadIdx.x;
    const int lane = t & 31;
    const int wid  = t >> 5;
    const int mw   = wid & 3;
    const int nw   = wid >> 2;
    const int b    = blockIdx.z;
    const int g    = blockIdx.y;
    const int i0   = blockIdx.x * 2;
    const int p0   = i0 * WW;               // pixel base

    // ---- phase 1a: stage A from pre-split g_xh/g_xl (u32 = 2 bf16) ----
    {
        const uint32_t* xh = (const uint32_t*)(g_xh + ((size_t)b * PIX + p0) * R);
        const uint32_t* xl = (const uint32_t*)(g_xl + ((size_t)b * PIX + p0) * R);
#pragma unroll
        for (int it = 0; it < 24; ++it) {
            int idx = it * 256 + t;
            int pix = idx >> 5, kp = idx & 31;
            ((uint32_t*)(Ah + pix * LDK))[kp] = xh[pix * 32 + kp];
            ((uint32_t*)(Al + pix * LDK))[kp] = xl[pix * 32 + kp];
        }
    }
    // ---- phase 1b: stage B = W2^g [64 cols(pad)][64 k] hi/lo ----
#pragma unroll
    for (int it = 0; it < 16; ++it) {
        int idx = it * 256 + t;
        int col = idx >> 6, r = idx & 63;
        float wv = (col < KT2) ? W2[((size_t)g * KT2 + col) * R + r] : 0.f;
        __nv_bfloat16 h = __float2bfloat16(wv);
        __nv_bfloat16 l = __float2bfloat16(wv - __bfloat162float(h));
        Bh[col * LDK + r] = h;
        Bl[col * LDK + r] = l;
    }
    __syncthreads();

    // ---- phase 1c: mma (K=64, 4 steps, 3 terms) ----
    float acc[3][4][4];
#pragma unroll
    for (int mf = 0; mf < 3; ++mf)
#pragma unroll
        for (int nf = 0; nf < 4; ++nf)
#pragma unroll
            for (int q = 0; q < 4; ++q) acc[mf][nf][q] = 0.f;

    const int ar = lane >> 2;
    const int ac = (lane & 3) * 2;
#pragma unroll
    for (int ks = 0; ks < 4; ++ks) {
        const int kb = ks * 16;
        uint32_t ah[3][4], al[3][4];
#pragma unroll
        for (int mf = 0; mf < 3; ++mf) {
            int rb = mw * 48 + mf * 16;
            const __nv_bfloat16* pa = Ah + (rb + ar) * LDK + kb + ac;
            ah[mf][0] = *(const uint32_t*)pa;
            ah[mf][1] = *(const uint32_t*)(pa + 8 * LDK);
            ah[mf][2] = *(const uint32_t*)(pa + 8);
            ah[mf][3] = *(const uint32_t*)(pa + 8 * LDK + 8);
            const __nv_bfloat16* pl = Al + (rb + ar) * LDK + kb + ac;
            al[mf][0] = *(const uint32_t*)pl;
            al[mf][1] = *(const uint32_t*)(pl + 8 * LDK);
            al[mf][2] = *(const uint32_t*)(pl + 8);
            al[mf][3] = *(const uint32_t*)(pl + 8 * LDK + 8);
        }
#pragma unroll
        for (int nf = 0; nf < 4; ++nf) {
            int colb = nw * 32 + nf * 8 + ar;
            const __nv_bfloat16* pb = Bh + colb * LDK + kb + ac;
            uint32_t bh0 = *(const uint32_t*)pb;
            uint32_t bh1 = *(const uint32_t*)(pb + 8);
            const __nv_bfloat16* pbl = Bl + colb * LDK + kb + ac;
            uint32_t bl0 = *(const uint32_t*)pbl;
            uint32_t bl1 = *(const uint32_t*)(pbl + 8);
#pragma unroll
            for (int mf = 0; mf < 3; ++mf) {
                float* cc = acc[mf][nf];
                mma_bf16(cc[0], cc[1], cc[2], cc[3],
                         ah[mf][0], ah[mf][1], ah[mf][2], ah[mf][3], bh0, bh1);
                mma_bf16(cc[0], cc[1], cc[2], cc[3],
                         ah[mf][0], ah[mf][1], ah[mf][2], ah[mf][3], bl0, bl1);
                mma_bf16(cc[0], cc[1], cc[2], cc[3],
                         al[mf][0], al[mf][1], al[mf][2], al[mf][3], bh0, bh1);
            }
        }
    }
    __syncthreads();   // acc in regs; smem now reusable

    // ---- phase 2: write Ds (cols<49) + stage feature tile ----
#pragma unroll
    for (int mf = 0; mf < 3; ++mf) {
        int row = mw * 48 + mf * 16 + ar;
#pragma unroll
        for (int nf = 0; nf < 4; ++nf) {
            int col = nw * 32 + nf * 8 + (lane & 3) * 2;
            if (col < KT2) {
                Ds[row * F_DS_LD + col]       = acc[mf][nf][0];
                Ds[(row + 8) * F_DS_LD + col] = acc[mf][nf][2];
            }
            if (col + 1 < KT2) {
                Ds[row * F_DS_LD + col + 1]       = acc[mf][nf][1];
                Ds[(row + 8) * F_DS_LD + col + 1] = acc[mf][nf][3];
            }
        }
    }
#pragma unroll
    for (int it = 0; it < 51; ++it) {
        int idx = it * 256 + t;          // 16*8*102 = 13056 = 51*256
        int ch  = idx / (8 * 102);
        int rem = idx - ch * (8 * 102);
        int rr  = rem / 102;
        int cc  = rem - rr * 102;
        int grow = i0 + rr - 3;
        int gcol = cc - 3;
        float v = 0.f;
        if (grow >= 0 && grow < HH && gcol >= 0 && gcol < WW)
            v = feat[(((size_t)b * C + g * GC + ch) * HH + grow) * WW + gcol];
        ft[(ch * 8 + rr) * F_FT_STRIDE + cc] = v;
    }
    __syncthreads();

    // ---- phase 3: involution + residual ----
    // team = row (2), per team 128 thr: u = ch-pair (8), seg = 6-col segment (16)
    const int team = t >> 7;
    const int tt   = t & 127;
    const int u    = tt >> 4;
    const int seg  = tt & 15;
    const int jb   = 6 * seg;
    const int i    = i0 + team;
    const int ch0  = 2 * u;

    const float* ft0 = ft + (ch0 * 8) * F_FT_STRIDE;
    const float* ft1 = ft + ((ch0 + 1) * 8) * F_FT_STRIDE;
    const float* dsb = Ds + (team * 96 + jb) * F_DS_LD;

    float o0[6], o1[6];
#pragma unroll
    for (int jj = 0; jj < 6; ++jj) {
        o0[jj] = ft0[(team + 3) * F_FT_STRIDE + 3 + jb + jj];   // residual
        o1[jj] = ft1[(team + 3) * F_FT_STRIDE + 3 + jb + jj];
    }
#pragma unroll
    for (int di = 0; di < KT; ++di) {
        float f0[12], f1[12];
        const float* r0p = ft0 + (team + di) * F_FT_STRIDE + jb;
        const float* r1p = ft1 + (team + di) * F_FT_STRIDE + jb;
#pragma unroll
        for (int q = 0; q < 12; ++q) { f0[q] = r0p[q]; f1[q] = r1p[q]; }
#pragma unroll
        for (int jj = 0; jj < 6; ++jj) {
            const float* dpj = dsb + jj * F_DS_LD + di * KT;
            float a0 = o0[jj], a1 = o1[jj];
#pragma unroll
            for (int dj = 0; dj < KT; ++dj) {
                float d = dpj[dj];
                a0 += f0[jj + dj] * d;
                a1 += f1[jj + dj] * d;
            }
            o0[jj] = a0; o1[jj] = a1;
        }
    }
    size_t ob = (((size_t)b * C + g * GC + ch0) * HH + i) * WW + jb;
#pragma unroll
    for (int jj = 0; jj < 6; ++jj) out[ob + jj]       = o0[jj];
#pragma unroll
    for (int jj = 0; jj < 6; ++jj) out[ob + PIX + jj] = o1[jj];
}

// ---------------------------------------------------------------------------
extern "C" void kernel_launch(void* const* d_in, const int* in_sizes, int n_in,
                              void* d_out, int out_size)
{
    const float* feat  = (const float*)d_in[0];
    const float* guide = (const float*)d_in[1];
    const float* W1    = (const float*)d_in[2];
    const float* gamma = (const float*)d_in[3];
    const float* beta  = (const float*)d_in[4];
    const float* mean  = (const float*)d_in[5];
    const float* var   = (const float*)d_in[6];
    const float* W2    = (const float*)d_in[7];
    float* out = (float*)d_out;

    cudaFuncSetAttribute(k_convs1, cudaFuncAttributeMaxDynamicSharedMemorySize, C1_SMEM);
    cudaFuncSetAttribute(k_fused,  cudaFuncAttributeMaxDynamicSharedMemorySize, F_SMEM);

    k_convs1<<<dim3(48, 8), 256, C1_SMEM>>>(guide, W1, gamma, beta, mean, var);
    k_fused<<<dim3(48, 16, 8), 256, F_SMEM>>>(feat, W2, out);
}

// round 8
// speedup vs baseline: 2.0783x; 1.0960x over previous
#include <cuda_runtime.h>
#include <cuda_bf16.h>
#include <cstdint>
#include <cstddef>

#define R 64        // reduced channels
#define C 256       // channels
#define HH 96
#define WW 96
#define PIX (HH*WW)
#define NG 16       // groups
#define GC 16       // group channels
#define KT 7
#define KT2 49

// x = relu(BN(W1 @ guide)), stored pre-split as bf16 hi/lo: [b][pix][r]
__device__ __nv_bfloat16 g_xh[(size_t)8 * PIX * R];
__device__ __nv_bfloat16 g_xl[(size_t)8 * PIX * R];

#define LDK 72                 // padded k-stride (bf16 elems) in smem tiles

// ---------------------------------------------------------------------------
// mma.sync m16n8k16 bf16 (row.col), fp32 accumulate (verified mapping, R5)
// ---------------------------------------------------------------------------
__device__ __forceinline__ void mma_bf16(
    float& c0, float& c1, float& c2, float& c3,
    uint32_t a0, uint32_t a1, uint32_t a2, uint32_t a3,
    uint32_t b0, uint32_t b1)
{
    asm volatile(
        "mma.sync.aligned.m16n8k16.row.col.f32.bf16.bf16.f32 "
        "{%0,%1,%2,%3}, {%4,%5,%6,%7}, {%8,%9}, {%0,%1,%2,%3};"
        : "+f"(c0), "+f"(c1), "+f"(c2), "+f"(c3)
        : "r"(a0), "r"(a1), "r"(a2), "r"(a3), "r"(b0), "r"(b1));
}
__device__ __forceinline__ void ldmat_x4(uint32_t& r0, uint32_t& r1,
                                         uint32_t& r2, uint32_t& r3, uint32_t a)
{
    asm volatile("ldmatrix.sync.aligned.m8n8.x4.shared.b16 {%0,%1,%2,%3}, [%4];"
                 : "=r"(r0), "=r"(r1), "=r"(r2), "=r"(r3) : "r"(a));
}
__device__ __forceinline__ uint32_t sptr(const void* p) {
    return (uint32_t)__cvta_generic_to_shared(p);
}

// ---------------------------------------------------------------------------
// Kernel 1: x = relu(BN(W1 @ guide)) via mma.sync, 3-term bf16 split.
// CTA: 256 thr = 8 warps (4M x 2N). D[192 pix][64 out], K=256 in 4 chunks.
// Fragment loads via ldmatrix.x4. Epilogue: BN+ReLU, bf16 hi/lo store.
// grid (48, 8), smem 72KB, 2 CTAs/SM.
// ---------------------------------------------------------------------------
#define C1_AH 0
#define C1_AL (192 * LDK)             // bf16 elems
#define C1_BH (2 * 192 * LDK)
#define C1_BL (2 * 192 * LDK + 64 * LDK)
#define C1_SMEM ((2 * 192 * LDK + 2 * 64 * LDK) * 2)   // 73728 bytes

__global__ __launch_bounds__(256, 2) void k_convs1(
    const float* __restrict__ guide, const float* __restrict__ W1,
    const float* __restrict__ gamma, const float* __restrict__ beta,
    const float* __restrict__ mean,  const float* __restrict__ var)
{
    extern __shared__ __nv_bfloat16 sm[];
    __nv_bfloat16* Ah = sm + C1_AH;
    __nv_bfloat16* Al = sm + C1_AL;
    __nv_bfloat16* Bh = sm + C1_BH;
    __nv_bfloat16* Bl = sm + C1_BL;
    __shared__ float sc[R], bi[R];

    const int t    = threadIdx.x;
    const int lane = t & 31;
    const int wid  = t >> 5;
    const int mw   = wid & 3;
    const int nw   = wid >> 2;
    const int b    = blockIdx.y;
    const int p0   = blockIdx.x * 192;

    if (t < R) {
        float iv = gamma[t] * rsqrtf(var[t] + 1e-5f);
        sc[t] = iv;
        bi[t] = beta[t] - mean[t] * iv;
    }

    float acc[3][4][4];
#pragma unroll
    for (int mf = 0; mf < 3; ++mf)
#pragma unroll
        for (int nf = 0; nf < 4; ++nf)
#pragma unroll
            for (int q = 0; q < 4; ++q) acc[mf][nf][q] = 0.f;

    // ldmatrix lane addressing
    const int l7  = lane & 7;
    const int sub = lane >> 3;
    const int a_row = mw * 48 + (sub & 1) * 8 + l7;   // + mf*16
    const int a_col = (sub >> 1) * 8;                 // + kb
    const int b_row = nw * 32 + (sub >> 1) * 8 + l7;  // + p*16
    const int b_col = (sub & 1) * 8;                  // + kb
    const uint32_t ah_base = sptr(Ah) + (a_row * LDK + a_col) * 2;
    const uint32_t al_base = sptr(Al) + (a_row * LDK + a_col) * 2;
    const uint32_t bh_base = sptr(Bh) + (b_row * LDK + b_col) * 2;
    const uint32_t bl_base = sptr(Bl) + (b_row * LDK + b_col) * 2;

    for (int kc = 0; kc < 4; ++kc) {
        __syncthreads();   // prior mma readers done (also orders sc/bi, iter 0)
        // stage A: guide^T[192 pix][64 k] hi/lo
#pragma unroll
        for (int it = 0; it < 48; ++it) {
            int idx = it * 256 + t;
            int k   = idx / 192;
            int pix = idx - k * 192;
            float v = guide[(size_t)b * C * PIX + (size_t)(kc * 64 + k) * PIX + p0 + pix];
            __nv_bfloat16 h = __float2bfloat16(v);
            __nv_bfloat16 l = __float2bfloat16(v - __bfloat162float(h));
            Ah[pix * LDK + k] = h;
            Al[pix * LDK + k] = l;
        }
        // stage B: W1[64 out][64 k] hi/lo
#pragma unroll
        for (int it = 0; it < 16; ++it) {
            int idx = it * 256 + t;
            int col = idx >> 6, r = idx & 63;
            float wv = W1[(size_t)col * C + kc * 64 + r];
            __nv_bfloat16 h = __float2bfloat16(wv);
            __nv_bfloat16 l = __float2bfloat16(wv - __bfloat162float(h));
            Bh[col * LDK + r] = h;
            Bl[col * LDK + r] = l;
        }
        __syncthreads();

#pragma unroll
        for (int ks = 0; ks < 4; ++ks) {
            const uint32_t ko = ks * 32;   // 16 bf16 = 32 bytes
            uint32_t ah[3][4], al[3][4];
#pragma unroll
            for (int mf = 0; mf < 3; ++mf) {
                ldmat_x4(ah[mf][0], ah[mf][1], ah[mf][2], ah[mf][3],
                         ah_base + mf * (16 * LDK * 2) + ko);
                ldmat_x4(al[mf][0], al[mf][1], al[mf][2], al[mf][3],
                         al_base + mf * (16 * LDK * 2) + ko);
            }
#pragma unroll
            for (int p = 0; p < 2; ++p) {
                uint32_t bh0, bh1, bh2, bh3, bl0, bl1, bl2, bl3;
                ldmat_x4(bh0, bh1, bh2, bh3, bh_base + p * (16 * LDK * 2) + ko);
                ldmat_x4(bl0, bl1, bl2, bl3, bl_base + p * (16 * LDK * 2) + ko);
#pragma unroll
                for (int mf = 0; mf < 3; ++mf) {
                    float* c0 = acc[mf][2 * p];
                    float* c1 = acc[mf][2 * p + 1];
                    mma_bf16(c0[0], c0[1], c0[2], c0[3],
                             ah[mf][0], ah[mf][1], ah[mf][2], ah[mf][3], bh0, bh1);
                    mma_bf16(c0[0], c0[1], c0[2], c0[3],
                             ah[mf][0], ah[mf][1], ah[mf][2], ah[mf][3], bl0, bl1);
                    mma_bf16(c0[0], c0[1], c0[2], c0[3],
                             al[mf][0], al[mf][1], al[mf][2], al[mf][3], bh0, bh1);
                    mma_bf16(c1[0], c1[1], c1[2], c1[3],
                             ah[mf][0], ah[mf][1], ah[mf][2], ah[mf][3], bh2, bh3);
                    mma_bf16(c1[0], c1[1], c1[2], c1[3],
                             ah[mf][0], ah[mf][1], ah[mf][2], ah[mf][3], bl2, bl3);
                    mma_bf16(c1[0], c1[1], c1[2], c1[3],
                             al[mf][0], al[mf][1], al[mf][2], al[mf][3], bh2, bh3);
                }
            }
        }
    }

    // epilogue: BN + ReLU + hi/lo split, store [b][pix][r] packed u32 (2 bf16)
    const int ar = lane >> 2;
#pragma unroll
    for (int mf = 0; mf < 3; ++mf) {
        int row = mw * 48 + mf * 16 + ar;
#pragma unroll
        for (int nf = 0; nf < 4; ++nf) {
            int col = nw * 32 + nf * 8 + (lane & 3) * 2;
            float s0 = sc[col], s1 = sc[col + 1];
            float b0 = bi[col], b1 = bi[col + 1];
#pragma unroll
            for (int half = 0; half < 2; ++half) {
                int r2 = row + half * 8;
                float v0 = fmaxf(acc[mf][nf][2 * half + 0] * s0 + b0, 0.f);
                float v1 = fmaxf(acc[mf][nf][2 * half + 1] * s1 + b1, 0.f);
                __nv_bfloat162 h2 = __floats2bfloat162_rn(v0, v1);
                __nv_bfloat162 l2 = __floats2bfloat162_rn(
                    v0 - __bfloat162float(h2.x), v1 - __bfloat162float(h2.y));
                size_t base = ((size_t)b * PIX + p0 + r2) * R + col;
                *(uint32_t*)(g_xh + base) = *(uint32_t*)&h2;
                *(uint32_t*)(g_xl + base) = *(uint32_t*)&l2;
            }
        }
    }
}

// ---------------------------------------------------------------------------
// Kernel 2 (fused): per CTA = (row pair i0, group g, batch b).
//   Phase 1: df[192 pix][49(pad64)] = x^T @ W2^g^T via mma (ldmatrix frags)
//   Phase 2: acc -> smem Ds[49 taps][196] (tap-major) ; feature tile [16][8][106]
//   Phase 3: involution + residual, float2-vectorized smem reads.
// grid (48, 16, 8), 256 thr, smem 92688B, 2 CTAs/SM.
// ---------------------------------------------------------------------------
#define F_AH 0
#define F_AL (192 * LDK)
#define F_BH (2 * 192 * LDK)
#define F_BL (2 * 192 * LDK + 64 * LDK)
#define F_FT_STRIDE 106
#define F_FT_FLOATS (GC * 8 * F_FT_STRIDE)          // 13568
#define F_DS_OFF    F_FT_FLOATS
#define F_DS_LD     196                              // tap stride (floats)
#define F_SMEM ((F_FT_FLOATS + KT2 * F_DS_LD) * 4)   // 92688 bytes

__global__ __launch_bounds__(256, 2) void k_fused(
    const float* __restrict__ feat, const float* __restrict__ W2,
    float* __restrict__ out)
{
    extern __shared__ __nv_bfloat16 sm[];
    __nv_bfloat16* Ah = sm + F_AH;
    __nv_bfloat16* Al = sm + F_AL;
    __nv_bfloat16* Bh = sm + F_BH;
    __nv_bfloat16* Bl = sm + F_BL;
    float* ft = (float*)sm;                 // phase-2/3 overlay
    float* Ds = (float*)sm + F_DS_OFF;      // [49][196]

    const int t    = threadIdx.x;
    const int lane = t & 31;
    const int wid  = t >> 5;
    const int mw   = wid & 3;
    const int nw   = wid >> 2;
    const int b    = blockIdx.z;
    const int g    = blockIdx.y;
    const int i0   = blockIdx.x * 2;
    const int p0   = i0 * WW;               // pixel base

    // ---- phase 1a: stage A from pre-split g_xh/g_xl (u32 = 2 bf16) ----
    {
        const uint32_t* xh = (const uint32_t*)(g_xh + ((size_t)b * PIX + p0) * R);
        const uint32_t* xl = (const uint32_t*)(g_xl + ((size_t)b * PIX + p0) * R);
#pragma unroll
        for (int it = 0; it < 24; ++it) {
            int idx = it * 256 + t;
            int pix = idx >> 5, kp = idx & 31;
            ((uint32_t*)(Ah + pix * LDK))[kp] = xh[pix * 32 + kp];
            ((uint32_t*)(Al + pix * LDK))[kp] = xl[pix * 32 + kp];
        }
    }
    // ---- phase 1b: stage B = W2^g [64 cols(pad)][64 k] hi/lo ----
#pragma unroll
    for (int it = 0; it < 16; ++it) {
        int idx = it * 256 + t;
        int col = idx >> 6, r = idx & 63;
        float wv = (col < KT2) ? W2[((size_t)g * KT2 + col) * R + r] : 0.f;
        __nv_bfloat16 h = __float2bfloat16(wv);
        __nv_bfloat16 l = __float2bfloat16(wv - __bfloat162float(h));
        Bh[col * LDK + r] = h;
        Bl[col * LDK + r] = l;
    }
    __syncthreads();

    // ---- phase 1c: mma (K=64, 4 steps, 3 terms), ldmatrix fragments ----
    float acc[3][4][4];
#pragma unroll
    for (int mf = 0; mf < 3; ++mf)
#pragma unroll
        for (int nf = 0; nf < 4; ++nf)
#pragma unroll
            for (int q = 0; q < 4; ++q) acc[mf][nf][q] = 0.f;

    {
        const int l7  = lane & 7;
        const int sub = lane >> 3;
        const int a_row = mw * 48 + (sub & 1) * 8 + l7;
        const int a_col = (sub >> 1) * 8;
        const int b_row = nw * 32 + (sub >> 1) * 8 + l7;
        const int b_col = (sub & 1) * 8;
        const uint32_t ah_base = sptr(Ah) + (a_row * LDK + a_col) * 2;
        const uint32_t al_base = sptr(Al) + (a_row * LDK + a_col) * 2;
        const uint32_t bh_base = sptr(Bh) + (b_row * LDK + b_col) * 2;
        const uint32_t bl_base = sptr(Bl) + (b_row * LDK + b_col) * 2;

#pragma unroll
        for (int ks = 0; ks < 4; ++ks) {
            const uint32_t ko = ks * 32;
            uint32_t ah[3][4], al[3][4];
#pragma unroll
            for (int mf = 0; mf < 3; ++mf) {
                ldmat_x4(ah[mf][0], ah[mf][1], ah[mf][2], ah[mf][3],
                         ah_base + mf * (16 * LDK * 2) + ko);
                ldmat_x4(al[mf][0], al[mf][1], al[mf][2], al[mf][3],
                         al_base + mf * (16 * LDK * 2) + ko);
            }
#pragma unroll
            for (int p = 0; p < 2; ++p) {
                uint32_t bh0, bh1, bh2, bh3, bl0, bl1, bl2, bl3;
                ldmat_x4(bh0, bh1, bh2, bh3, bh_base + p * (16 * LDK * 2) + ko);
                ldmat_x4(bl0, bl1, bl2, bl3, bl_base + p * (16 * LDK * 2) + ko);
#pragma unroll
                for (int mf = 0; mf < 3; ++mf) {
                    float* c0 = acc[mf][2 * p];
                    float* c1 = acc[mf][2 * p + 1];
                    mma_bf16(c0[0], c0[1], c0[2], c0[3],
                             ah[mf][0], ah[mf][1], ah[mf][2], ah[mf][3], bh0, bh1);
                    mma_bf16(c0[0], c0[1], c0[2], c0[3],
                             ah[mf][0], ah[mf][1], ah[mf][2], ah[mf][3], bl0, bl1);
                    mma_bf16(c0[0], c0[1], c0[2], c0[3],
                             al[mf][0], al[mf][1], al[mf][2], al[mf][3], bh0, bh1);
                    mma_bf16(c1[0], c1[1], c1[2], c1[3],
                             ah[mf][0], ah[mf][1], ah[mf][2], ah[mf][3], bh2, bh3);
                    mma_bf16(c1[0], c1[1], c1[2], c1[3],
                             ah[mf][0], ah[mf][1], ah[mf][2], ah[mf][3], bl2, bl3);
                    mma_bf16(c1[0], c1[1], c1[2], c1[3],
                             al[mf][0], al[mf][1], al[mf][2], al[mf][3], bh2, bh3);
                }
            }
        }
    }
    __syncthreads();   // acc in regs; smem now reusable

    // ---- phase 2: write Ds tap-major (cols<49) + stage feature tile ----
    {
        const int ar = lane >> 2;
#pragma unroll
        for (int mf = 0; mf < 3; ++mf) {
            int row = mw * 48 + mf * 16 + ar;
#pragma unroll
            for (int nf = 0; nf < 4; ++nf) {
                int col = nw * 32 + nf * 8 + (lane & 3) * 2;
                if (col < KT2) {
                    Ds[col * F_DS_LD + row]     = acc[mf][nf][0];
                    Ds[col * F_DS_LD + row + 8] = acc[mf][nf][2];
                }
                if (col + 1 < KT2) {
                    Ds[(col + 1) * F_DS_LD + row]     = acc[mf][nf][1];
                    Ds[(col + 1) * F_DS_LD + row + 8] = acc[mf][nf][3];
                }
            }
        }
    }
#pragma unroll
    for (int it = 0; it < 51; ++it) {
        int idx = it * 256 + t;          // 16*8*102 = 13056 = 51*256
        int ch  = idx / (8 * 102);
        int rem = idx - ch * (8 * 102);
        int rr  = rem / 102;
        int cc  = rem - rr * 102;
        int grow = i0 + rr - 3;
        int gcol = cc - 3;
        float v = 0.f;
        if (grow >= 0 && grow < HH && gcol >= 0 && gcol < WW)
            v = feat[(((size_t)b * C + g * GC + ch) * HH + grow) * WW + gcol];
        ft[(ch * 8 + rr) * F_FT_STRIDE + cc] = v;
    }
    __syncthreads();

    // ---- phase 3: involution + residual (float2-vectorized smem reads) ----
    const int team = t >> 7;
    const int tt   = t & 127;
    const int u    = tt >> 4;
    const int seg  = tt & 15;
    const int jb   = 6 * seg;               // even -> 8B aligned windows
    const int i    = i0 + team;
    const int ch0  = 2 * u;

    const float* ft0 = ft + (ch0 * 8) * F_FT_STRIDE;
    const float* ft1 = ft + ((ch0 + 1) * 8) * F_FT_STRIDE;
    const float* dk  = Ds + team * 96 + jb;

    float o0[6], o1[6];
#pragma unroll
    for (int jj = 0; jj < 6; ++jj) {
        o0[jj] = ft0[(team + 3) * F_FT_STRIDE + 3 + jb + jj];   // residual
        o1[jj] = ft1[(team + 3) * F_FT_STRIDE + 3 + jb + jj];
    }
#pragma unroll
    for (int di = 0; di < KT; ++di) {
        float f0[12], f1[12];
        const float* r0p = ft0 + (team + di) * F_FT_STRIDE + jb;
        const float* r1p = ft1 + (team + di) * F_FT_STRIDE + jb;
#pragma unroll
        for (int q = 0; q < 6; ++q) {
            float2 v0 = *(const float2*)(r0p + 2 * q);
            float2 v1 = *(const float2*)(r1p + 2 * q);
            f0[2 * q] = v0.x; f0[2 * q + 1] = v0.y;
            f1[2 * q] = v1.x; f1[2 * q + 1] = v1.y;
        }
#pragma unroll
        for (int dj = 0; dj < KT; ++dj) {
            const float* dp = dk + (di * KT + dj) * F_DS_LD;
            float2 d0 = *(const float2*)(dp);
            float2 d1 = *(const float2*)(dp + 2);
            float2 d2 = *(const float2*)(dp + 4);
            o0[0] += f0[dj]     * d0.x;  o1[0] += f1[dj]     * d0.x;
            o0[1] += f0[dj + 1] * d0.y;  o1[1] += f1[dj + 1] * d0.y;
            o0[2] += f0[dj + 2] * d1.x;  o1[2] += f1[dj + 2] * d1.x;
            o0[3] += f0[dj + 3] * d1.y;  o1[3] += f1[dj + 3] * d1.y;
            o0[4] += f0[dj + 4] * d2.x;  o1[4] += f1[dj + 4] * d2.x;
            o0[5] += f0[dj + 5] * d2.y;  o1[5] += f1[dj + 5] * d2.y;
        }
    }
    size_t ob = (((size_t)b * C + g * GC + ch0) * HH + i) * WW + jb;
#pragma unroll
    for (int q = 0; q < 3; ++q) {
        float2 v0 = make_float2(o0[2 * q], o0[2 * q + 1]);
        float2 v1 = make_float2(o1[2 * q], o1[2 * q + 1]);
        *(float2*)(out + ob + 2 * q)       = v0;
        *(float2*)(out + ob + PIX + 2 * q) = v1;
    }
}

// ---------------------------------------------------------------------------
extern "C" void kernel_launch(void* const* d_in, const int* in_sizes, int n_in,
                              void* d_out, int out_size)
{
    const float* feat  = (const float*)d_in[0];
    const float* guide = (const float*)d_in[1];
    const float* W1    = (const float*)d_in[2];
    const float* gamma = (const float*)d_in[3];
    const float* beta  = (const float*)d_in[4];
    const float* mean  = (const float*)d_in[5];
    const float* var   = (const float*)d_in[6];
    const float* W2    = (const float*)d_in[7];
    float* out = (float*)d_out;

    cudaFuncSetAttribute(k_convs1, cudaFuncAttributeMaxDynamicSharedMemorySize, C1_SMEM);
    cudaFuncSetAttribute(k_fused,  cudaFuncAttributeMaxDynamicSharedMemorySize, F_SMEM);

    k_convs1<<<dim3(48, 8), 256, C1_SMEM>>>(guide, W1, gamma, beta, mean, var);
    k_fused<<<dim3(48, 16, 8), 256, F_SMEM>>>(feat, W2, out);
}